// round 1
// baseline (speedup 1.0000x reference)
#include <cuda_runtime.h>
#include <math.h>

#define BB 2
#define SS 2048
#define DD 768
#define PP 16

// -------- scratch (no allocations allowed) --------
__device__ float g_q[BB * SS * DD];
__device__ float g_k[BB * SS * DD];
__device__ float g_v[BB * SS * DD];
__device__ float g_sc[BB * SS * SS];   // 8,388,608 floats = 33.5 MB
__device__ int   g_idx[BB * PP];

// -------- patch index decode (int64 vs int32 robust) --------
__global__ void decode_idx_kernel(const int* __restrict__ raw) {
    // int64 little-endian: raw[2i]=value, raw[2i+1]=0 (values in [0, 2048))
    // int32: raw[1] = patch_indices[0][1] >= 1 (strictly increasing, >=1)
    bool is64 = (raw[1] == 0);
    int t = threadIdx.x;
    if (t < BB * PP) g_idx[t] = is64 ? raw[2 * t] : raw[t];
}

// ============================================================
// Kernel 1: QKV projection. C[M,N] = X[M,K] @ W[K,N] + bias
// M = BB*SS = 4096, N = K = DD = 768. blockIdx.z selects q/k/v.
// 64x64 tile, BK=16, 256 threads, 4x4 microtile.
// ============================================================
__global__ __launch_bounds__(256) void qkv_kernel(
    const float* __restrict__ x,
    const float* __restrict__ Wq, const float* __restrict__ bq,
    const float* __restrict__ Wk, const float* __restrict__ bk,
    const float* __restrict__ Wv, const float* __restrict__ bv)
{
    const float* W; const float* bias; float* out;
    if (blockIdx.z == 0)      { W = Wq; bias = bq; out = g_q; }
    else if (blockIdx.z == 1) { W = Wk; bias = bk; out = g_k; }
    else                      { W = Wv; bias = bv; out = g_v; }

    __shared__ float As[16][64];
    __shared__ float Bs[16][64];

    const int tid = threadIdx.x;
    const int tx = tid & 15, ty = tid >> 4;
    const int m0 = blockIdx.y * 64;
    const int n0 = blockIdx.x * 64;

    const int la_row = tid >> 2;        // 0..63 (m)
    const int la_f4  = tid & 3;         // 0..3  (k float4 chunk)
    const int lb_row = tid >> 4;        // 0..15 (k)
    const int lb_col = (tid & 15) * 4;  // n offset

    float acc[4][4] = {};

    for (int k0 = 0; k0 < DD; k0 += 16) {
        float4 av = *(const float4*)&x[(m0 + la_row) * DD + k0 + la_f4 * 4];
        As[la_f4 * 4 + 0][la_row] = av.x;
        As[la_f4 * 4 + 1][la_row] = av.y;
        As[la_f4 * 4 + 2][la_row] = av.z;
        As[la_f4 * 4 + 3][la_row] = av.w;
        float4 wv4 = *(const float4*)&W[(k0 + lb_row) * DD + n0 + lb_col];
        *(float4*)&Bs[lb_row][lb_col] = wv4;
        __syncthreads();
        #pragma unroll
        for (int kk = 0; kk < 16; ++kk) {
            float4 a = *(const float4*)&As[kk][ty * 4];
            float4 b = *(const float4*)&Bs[kk][tx * 4];
            float ar[4] = {a.x, a.y, a.z, a.w};
            float br[4] = {b.x, b.y, b.z, b.w};
            #pragma unroll
            for (int i = 0; i < 4; ++i)
                #pragma unroll
                for (int j = 0; j < 4; ++j)
                    acc[i][j] += ar[i] * br[j];
        }
        __syncthreads();
    }

    float4 bias4 = *(const float4*)&bias[n0 + tx * 4];
    #pragma unroll
    for (int i = 0; i < 4; ++i) {
        int m = m0 + ty * 4 + i;
        float4 o;
        o.x = acc[i][0] + bias4.x;
        o.y = acc[i][1] + bias4.y;
        o.z = acc[i][2] + bias4.z;
        o.w = acc[i][3] + bias4.w;
        *(float4*)&out[m * DD + n0 + tx * 4] = o;
    }
}

// ============================================================
// Kernel 2: scores[b,q,j] = scale * Q[b,q,:] . K[b,j,:]   (A @ B^T)
// ============================================================
__global__ __launch_bounds__(256) void scores_kernel()
{
    const int b = blockIdx.z;
    const float* Q = g_q + b * SS * DD;
    const float* K = g_k + b * SS * DD;
    float* Sc = g_sc + (size_t)b * SS * SS;

    __shared__ float As[16][64];
    __shared__ float Bs[16][64];

    const int tid = threadIdx.x;
    const int tx = tid & 15, ty = tid >> 4;
    const int m0 = blockIdx.y * 64;   // query rows
    const int n0 = blockIdx.x * 64;   // key rows

    const int la_row = tid >> 2;
    const int la_f4  = tid & 3;

    float acc[4][4] = {};

    for (int k0 = 0; k0 < DD; k0 += 16) {
        float4 av = *(const float4*)&Q[(m0 + la_row) * DD + k0 + la_f4 * 4];
        As[la_f4 * 4 + 0][la_row] = av.x;
        As[la_f4 * 4 + 1][la_row] = av.y;
        As[la_f4 * 4 + 2][la_row] = av.z;
        As[la_f4 * 4 + 3][la_row] = av.w;
        float4 kv4 = *(const float4*)&K[(n0 + la_row) * DD + k0 + la_f4 * 4];
        Bs[la_f4 * 4 + 0][la_row] = kv4.x;
        Bs[la_f4 * 4 + 1][la_row] = kv4.y;
        Bs[la_f4 * 4 + 2][la_row] = kv4.z;
        Bs[la_f4 * 4 + 3][la_row] = kv4.w;
        __syncthreads();
        #pragma unroll
        for (int kk = 0; kk < 16; ++kk) {
            float4 a = *(const float4*)&As[kk][ty * 4];
            float4 b4 = *(const float4*)&Bs[kk][tx * 4];
            float ar[4] = {a.x, a.y, a.z, a.w};
            float br[4] = {b4.x, b4.y, b4.z, b4.w};
            #pragma unroll
            for (int i = 0; i < 4; ++i)
                #pragma unroll
                for (int j = 0; j < 4; ++j)
                    acc[i][j] += ar[i] * br[j];
        }
        __syncthreads();
    }

    const float scale = 0.03608439182435161f;  // 768^-0.5
    #pragma unroll
    for (int i = 0; i < 4; ++i) {
        int m = m0 + ty * 4 + i;
        float4 o;
        o.x = acc[i][0] * scale;
        o.y = acc[i][1] * scale;
        o.z = acc[i][2] * scale;
        o.w = acc[i][3] * scale;
        *(float4*)&Sc[(size_t)m * SS + n0 + tx * 4] = o;
    }
}

// ============================================================
// Kernel 3: segment-wise softmax, in place on g_sc.
// Patch segments are disjoint in j, so in-place is safe.
// One warp per (b, p, q).
// ============================================================
__global__ __launch_bounds__(256) void softmax_kernel()
{
    const int b = blockIdx.z;
    const int p = blockIdx.y;
    const int warp = threadIdx.x >> 5;
    const int lane = threadIdx.x & 31;
    const int q = blockIdx.x * 8 + warp;

    const int start = g_idx[b * PP + p];
    const int end   = (p == PP - 1) ? SS : g_idx[b * PP + p + 1];

    float* row = g_sc + ((size_t)b * SS + q) * SS;

    float m = -INFINITY;
    for (int j = start + lane; j < end; j += 32) m = fmaxf(m, row[j]);
    #pragma unroll
    for (int o = 16; o; o >>= 1) m = fmaxf(m, __shfl_xor_sync(0xFFFFFFFFu, m, o));

    float s = 0.f;
    for (int j = start + lane; j < end; j += 32) s += __expf(row[j] - m);
    #pragma unroll
    for (int o = 16; o; o >>= 1) s += __shfl_xor_sync(0xFFFFFFFFu, s, o);

    float inv = 1.f / s;
    for (int j = start + lane; j < end; j += 32) row[j] = __expf(row[j] - m) * inv;
}

// ============================================================
// Kernel 4: out[b,p,q,:] = P[b,q,start:end] @ V[b,start:end,:]
// grid.z = b*PP+p, variable-length K loop with guards.
// ============================================================
__global__ __launch_bounds__(256) void av_kernel(float* __restrict__ out)
{
    const int bp = blockIdx.z;
    const int b = bp / PP, p = bp % PP;
    const int start = g_idx[b * PP + p];
    const int end   = (p == PP - 1) ? SS : g_idx[b * PP + p + 1];
    const int L = end - start;

    const int m0 = blockIdx.y * 64;   // queries
    const int n0 = blockIdx.x * 64;   // head dims
    const float* A = g_sc + (size_t)b * SS * SS;
    const float* V = g_v + b * SS * DD;

    __shared__ float As[16][64];
    __shared__ float Bs[16][64];

    const int tid = threadIdx.x;
    const int tx = tid & 15, ty = tid >> 4;

    const int la_row = tid >> 2;        // m (0..63)
    const int la_c4  = (tid & 3) * 4;   // kk base
    const int lb_row = tid >> 4;        // kk (0..15)
    const int lb_col = (tid & 15) * 4;  // n offset

    float acc[4][4] = {};

    for (int k0 = 0; k0 < L; k0 += 16) {
        // A tile (probabilities): unaligned start -> scalar guarded loads
        #pragma unroll
        for (int ii = 0; ii < 4; ++ii) {
            int kk = la_c4 + ii;
            int j = start + k0 + kk;
            As[kk][la_row] = (j < end) ? A[(size_t)(m0 + la_row) * SS + j] : 0.f;
        }
        // V tile: row j, cols aligned -> float4
        {
            int j = start + k0 + lb_row;
            float4 v4 = {0.f, 0.f, 0.f, 0.f};
            if (j < end) v4 = *(const float4*)&V[(size_t)j * DD + n0 + lb_col];
            *(float4*)&Bs[lb_row][lb_col] = v4;
        }
        __syncthreads();
        #pragma unroll
        for (int kk = 0; kk < 16; ++kk) {
            float4 a = *(const float4*)&As[kk][ty * 4];
            float4 b4 = *(const float4*)&Bs[kk][tx * 4];
            float ar[4] = {a.x, a.y, a.z, a.w};
            float br[4] = {b4.x, b4.y, b4.z, b4.w};
            #pragma unroll
            for (int i = 0; i < 4; ++i)
                #pragma unroll
                for (int j2 = 0; j2 < 4; ++j2)
                    acc[i][j2] += ar[i] * br[j2];
        }
        __syncthreads();
    }

    #pragma unroll
    for (int i = 0; i < 4; ++i) {
        int m = m0 + ty * 4 + i;
        float4 o = {acc[i][0], acc[i][1], acc[i][2], acc[i][3]};
        *(float4*)&out[((size_t)bp * SS + m) * DD + n0 + tx * 4] = o;
    }
}

// ============================================================
extern "C" void kernel_launch(void* const* d_in, const int* in_sizes, int n_in,
                              void* d_out, int out_size)
{
    const float* x   = (const float*)d_in[0];
    const int*   raw = (const int*)d_in[1];   // patch_indices (int32 or int64)
    const float* Wq  = (const float*)d_in[2];
    const float* bq  = (const float*)d_in[3];
    const float* Wk  = (const float*)d_in[4];
    const float* bk  = (const float*)d_in[5];
    const float* Wv  = (const float*)d_in[6];
    const float* bv  = (const float*)d_in[7];
    float* out = (float*)d_out;

    decode_idx_kernel<<<1, 64>>>(raw);
    qkv_kernel<<<dim3(DD / 64, (BB * SS) / 64, 3), 256>>>(x, Wq, bq, Wk, bk, Wv, bv);
    scores_kernel<<<dim3(SS / 64, SS / 64, BB), 256>>>();
    softmax_kernel<<<dim3(SS / 8, PP, BB), 256>>>();
    av_kernel<<<dim3(DD / 64, SS / 64, BB * PP), 256>>>(out);
}

// round 4
// speedup vs baseline: 3.1240x; 3.1240x over previous
#include <cuda_runtime.h>
#include <math.h>
#include <stdint.h>

#define BB 2
#define SS 2048
#define DD 768
#define PP 16

// -------- scratch --------
__device__ float g_q[BB * SS * DD];
__device__ float g_k[BB * SS * DD];
__device__ float g_v[BB * SS * DD];
__device__ float g_sc[BB * SS * SS];
__device__ int   g_idx[BB * PP];

__global__ void decode_idx_kernel(const int* __restrict__ raw) {
    bool is64 = (raw[1] == 0);
    int t = threadIdx.x;
    if (t < BB * PP) g_idx[t] = is64 ? raw[2 * t] : raw[t];
}

// -------- tf32 helpers --------
__device__ __forceinline__ uint32_t f2tf(float f) {
    uint32_t u;
    asm("cvt.rna.tf32.f32 %0, %1;" : "=r"(u) : "f"(f));
    return u;
}

__device__ __forceinline__ void mma_tf32(float* c, const uint32_t* a, const uint32_t* b) {
    asm volatile(
        "mma.sync.aligned.m16n8k8.row.col.f32.tf32.tf32.f32 "
        "{%0,%1,%2,%3},{%4,%5,%6,%7},{%8,%9},{%0,%1,%2,%3};\n"
        : "+f"(c[0]), "+f"(c[1]), "+f"(c[2]), "+f"(c[3])
        : "r"(a[0]), "r"(a[1]), "r"(a[2]), "r"(a[3]), "r"(b[0]), "r"(b[1]));
}

// ============================================================
// Kernel 1: QKV.  C[M,N] = X[M,K] @ W[K,N] + bias, M=4096, N=K=768
// CTA tile 128x128, BK=32, 256 thr (8 warps 2x4), warp tile 64x32.
// ============================================================
__global__ __launch_bounds__(256, 2) void qkv_kernel(
    const float* __restrict__ x,
    const float* __restrict__ Wq, const float* __restrict__ bq,
    const float* __restrict__ Wk, const float* __restrict__ bk,
    const float* __restrict__ Wv, const float* __restrict__ bv)
{
    const float* W; const float* bias; float* out;
    if (blockIdx.z == 0)      { W = Wq; bias = bq; out = g_q; }
    else if (blockIdx.z == 1) { W = Wk; bias = bk; out = g_k; }
    else                      { W = Wv; bias = bv; out = g_v; }

    __shared__ uint32_t As[128][36];   // [m][k]
    __shared__ uint32_t Bs[32][136];   // [k][n]

    const int tid  = threadIdx.x;
    const int lane = tid & 31;
    const int warp = tid >> 5;
    const int wm = warp >> 2, wn = warp & 3;   // 2 x 4
    const int m0 = blockIdx.y * 128;
    const int n0 = blockIdx.x * 128;

    float acc[4][4][4] = {};

    for (int k0 = 0; k0 < DD; k0 += 32) {
        // load A tile: 128x32, float4 along k
        #pragma unroll
        for (int i = 0; i < 4; ++i) {
            int f4 = tid + i * 256;
            int r = f4 >> 3, c4 = f4 & 7;
            float4 v = *(const float4*)&x[(size_t)(m0 + r) * DD + k0 + c4 * 4];
            As[r][c4 * 4 + 0] = f2tf(v.x); As[r][c4 * 4 + 1] = f2tf(v.y);
            As[r][c4 * 4 + 2] = f2tf(v.z); As[r][c4 * 4 + 3] = f2tf(v.w);
        }
        // load B tile: 32x128, float4 along n
        #pragma unroll
        for (int i = 0; i < 4; ++i) {
            int f4 = tid + i * 256;
            int r = f4 >> 5, c4 = f4 & 31;
            float4 v = *(const float4*)&W[(size_t)(k0 + r) * DD + n0 + c4 * 4];
            Bs[r][c4 * 4 + 0] = f2tf(v.x); Bs[r][c4 * 4 + 1] = f2tf(v.y);
            Bs[r][c4 * 4 + 2] = f2tf(v.z); Bs[r][c4 * 4 + 3] = f2tf(v.w);
        }
        __syncthreads();

        #pragma unroll
        for (int ks = 0; ks < 32; ks += 8) {
            uint32_t a[4][4], b[4][2];
            #pragma unroll
            for (int mi = 0; mi < 4; ++mi) {
                int r = wm * 64 + mi * 16 + (lane >> 2);
                int c = ks + (lane & 3);
                a[mi][0] = As[r][c];     a[mi][1] = As[r + 8][c];
                a[mi][2] = As[r][c + 4]; a[mi][3] = As[r + 8][c + 4];
            }
            #pragma unroll
            for (int ni = 0; ni < 4; ++ni) {
                int c = wn * 32 + ni * 8 + (lane >> 2);
                int r = ks + (lane & 3);
                b[ni][0] = Bs[r][c]; b[ni][1] = Bs[r + 4][c];
            }
            #pragma unroll
            for (int mi = 0; mi < 4; ++mi)
                #pragma unroll
                for (int ni = 0; ni < 4; ++ni)
                    mma_tf32(acc[mi][ni], a[mi], b[ni]);
        }
        __syncthreads();
    }

    // epilogue + bias
    #pragma unroll
    for (int mi = 0; mi < 4; ++mi) {
        #pragma unroll
        for (int ni = 0; ni < 4; ++ni) {
            int r = m0 + wm * 64 + mi * 16 + (lane >> 2);
            int c = n0 + wn * 32 + ni * 8 + (lane & 3) * 2;
            float2 o0 = {acc[mi][ni][0] + bias[c], acc[mi][ni][1] + bias[c + 1]};
            float2 o1 = {acc[mi][ni][2] + bias[c], acc[mi][ni][3] + bias[c + 1]};
            *(float2*)&out[(size_t)r * DD + c] = o0;
            *(float2*)&out[(size_t)(r + 8) * DD + c] = o1;
        }
    }
}

// ============================================================
// Kernel 2: scores = scale * Q @ K^T.  K stored untransposed in
// smem [n][k] — exactly the col-major B the mma wants.
// ============================================================
__global__ __launch_bounds__(256, 2) void scores_kernel()
{
    const int b = blockIdx.z;
    const float* Q = g_q + (size_t)b * SS * DD;
    const float* K = g_k + (size_t)b * SS * DD;
    float* Sc = g_sc + (size_t)b * SS * SS;

    __shared__ uint32_t Qs[128][36];   // [m][k]
    __shared__ uint32_t Ks[128][36];   // [n][k]

    const int tid  = threadIdx.x;
    const int lane = tid & 31;
    const int warp = tid >> 5;
    const int wm = warp >> 2, wn = warp & 3;
    const int m0 = blockIdx.y * 128;
    const int n0 = blockIdx.x * 128;

    float acc[4][4][4] = {};

    for (int k0 = 0; k0 < DD; k0 += 32) {
        #pragma unroll
        for (int i = 0; i < 4; ++i) {
            int f4 = tid + i * 256;
            int r = f4 >> 3, c4 = f4 & 7;
            float4 v = *(const float4*)&Q[(size_t)(m0 + r) * DD + k0 + c4 * 4];
            Qs[r][c4 * 4 + 0] = f2tf(v.x); Qs[r][c4 * 4 + 1] = f2tf(v.y);
            Qs[r][c4 * 4 + 2] = f2tf(v.z); Qs[r][c4 * 4 + 3] = f2tf(v.w);
            float4 w = *(const float4*)&K[(size_t)(n0 + r) * DD + k0 + c4 * 4];
            Ks[r][c4 * 4 + 0] = f2tf(w.x); Ks[r][c4 * 4 + 1] = f2tf(w.y);
            Ks[r][c4 * 4 + 2] = f2tf(w.z); Ks[r][c4 * 4 + 3] = f2tf(w.w);
        }
        __syncthreads();

        #pragma unroll
        for (int ks = 0; ks < 32; ks += 8) {
            uint32_t a[4][4], bfr[4][2];
            #pragma unroll
            for (int mi = 0; mi < 4; ++mi) {
                int r = wm * 64 + mi * 16 + (lane >> 2);
                int c = ks + (lane & 3);
                a[mi][0] = Qs[r][c];     a[mi][1] = Qs[r + 8][c];
                a[mi][2] = Qs[r][c + 4]; a[mi][3] = Qs[r + 8][c + 4];
            }
            #pragma unroll
            for (int ni = 0; ni < 4; ++ni) {
                int n = wn * 32 + ni * 8 + (lane >> 2);
                int c = ks + (lane & 3);
                bfr[ni][0] = Ks[n][c]; bfr[ni][1] = Ks[n][c + 4];
            }
            #pragma unroll
            for (int mi = 0; mi < 4; ++mi)
                #pragma unroll
                for (int ni = 0; ni < 4; ++ni)
                    mma_tf32(acc[mi][ni], a[mi], bfr[ni]);
        }
        __syncthreads();
    }

    const float scale = 0.03608439182435161f;
    #pragma unroll
    for (int mi = 0; mi < 4; ++mi) {
        #pragma unroll
        for (int ni = 0; ni < 4; ++ni) {
            int r = m0 + wm * 64 + mi * 16 + (lane >> 2);
            int c = n0 + wn * 32 + ni * 8 + (lane & 3) * 2;
            float2 o0 = {acc[mi][ni][0] * scale, acc[mi][ni][1] * scale};
            float2 o1 = {acc[mi][ni][2] * scale, acc[mi][ni][3] * scale};
            *(float2*)&Sc[(size_t)r * SS + c] = o0;
            *(float2*)&Sc[(size_t)(r + 8) * SS + c] = o1;
        }
    }
}

// ============================================================
// Kernel 3: segment softmax (unchanged, 24us)
// ============================================================
__global__ __launch_bounds__(256) void softmax_kernel()
{
    const int b = blockIdx.z;
    const int p = blockIdx.y;
    const int warp = threadIdx.x >> 5;
    const int lane = threadIdx.x & 31;
    const int q = blockIdx.x * 8 + warp;

    const int start = g_idx[b * PP + p];
    const int end   = (p == PP - 1) ? SS : g_idx[b * PP + p + 1];

    float* row = g_sc + ((size_t)b * SS + q) * SS;

    float m = -INFINITY;
    for (int j = start + lane; j < end; j += 32) m = fmaxf(m, row[j]);
    #pragma unroll
    for (int o = 16; o; o >>= 1) m = fmaxf(m, __shfl_xor_sync(0xFFFFFFFFu, m, o));

    float s = 0.f;
    for (int j = start + lane; j < end; j += 32) s += __expf(row[j] - m);
    #pragma unroll
    for (int o = 16; o; o >>= 1) s += __shfl_xor_sync(0xFFFFFFFFu, s, o);

    float inv = 1.f / s;
    for (int j = start + lane; j < end; j += 32) row[j] = __expf(row[j] - m) * inv;
}

// ============================================================
// Kernel 4: out[bp] = P[:, start:end] @ V[start:end, :]
// ============================================================
__global__ __launch_bounds__(256, 2) void av_kernel(float* __restrict__ out)
{
    const int bp = blockIdx.z;
    const int b = bp / PP, p = bp % PP;
    const int start = g_idx[b * PP + p];
    const int end   = (p == PP - 1) ? SS : g_idx[b * PP + p + 1];
    const int L = end - start;

    const int m0 = blockIdx.y * 128;   // queries
    const int n0 = blockIdx.x * 128;   // head dims
    const float* A = g_sc + (size_t)b * SS * SS;
    const float* V = g_v + (size_t)b * SS * DD;

    __shared__ uint32_t As[128][36];   // [m][k]
    __shared__ uint32_t Bs[32][136];   // [k][n]

    const int tid  = threadIdx.x;
    const int lane = tid & 31;
    const int warp = tid >> 5;
    const int wm = warp >> 2, wn = warp & 3;

    float acc[4][4][4] = {};

    for (int k0 = 0; k0 < L; k0 += 32) {
        // A tile: scalar guarded loads (unaligned segment start)
        #pragma unroll
        for (int i = 0; i < 16; ++i) {
            int sid = tid + i * 256;
            int m = sid >> 5, k = sid & 31;
            int j = start + k0 + k;
            float v = (j < end) ? A[(size_t)(m0 + m) * SS + j] : 0.f;
            As[m][k] = f2tf(v);
        }
        // V tile: float4 along n, row guarded
        #pragma unroll
        for (int i = 0; i < 4; ++i) {
            int f4 = tid + i * 256;
            int r = f4 >> 5, c4 = f4 & 31;
            int j = start + k0 + r;
            float4 v = {0.f, 0.f, 0.f, 0.f};
            if (j < end) v = *(const float4*)&V[(size_t)j * DD + n0 + c4 * 4];
            Bs[r][c4 * 4 + 0] = f2tf(v.x); Bs[r][c4 * 4 + 1] = f2tf(v.y);
            Bs[r][c4 * 4 + 2] = f2tf(v.z); Bs[r][c4 * 4 + 3] = f2tf(v.w);
        }
        __syncthreads();

        #pragma unroll
        for (int ks = 0; ks < 32; ks += 8) {
            uint32_t a[4][4], bfr[4][2];
            #pragma unroll
            for (int mi = 0; mi < 4; ++mi) {
                int r = wm * 64 + mi * 16 + (lane >> 2);
                int c = ks + (lane & 3);
                a[mi][0] = As[r][c];     a[mi][1] = As[r + 8][c];
                a[mi][2] = As[r][c + 4]; a[mi][3] = As[r + 8][c + 4];
            }
            #pragma unroll
            for (int ni = 0; ni < 4; ++ni) {
                int c = wn * 32 + ni * 8 + (lane >> 2);
                int r = ks + (lane & 3);
                bfr[ni][0] = Bs[r][c]; bfr[ni][1] = Bs[r + 4][c];
            }
            #pragma unroll
            for (int mi = 0; mi < 4; ++mi)
                #pragma unroll
                for (int ni = 0; ni < 4; ++ni)
                    mma_tf32(acc[mi][ni], a[mi], bfr[ni]);
        }
        __syncthreads();
    }

    #pragma unroll
    for (int mi = 0; mi < 4; ++mi) {
        #pragma unroll
        for (int ni = 0; ni < 4; ++ni) {
            int r = m0 + wm * 64 + mi * 16 + (lane >> 2);
            int c = n0 + wn * 32 + ni * 8 + (lane & 3) * 2;
            float2 o0 = {acc[mi][ni][0], acc[mi][ni][1]};
            float2 o1 = {acc[mi][ni][2], acc[mi][ni][3]};
            *(float2*)&out[((size_t)bp * SS + r) * DD + c] = o0;
            *(float2*)&out[((size_t)bp * SS + r + 8) * DD + c] = o1;
        }
    }
}

// ============================================================
extern "C" void kernel_launch(void* const* d_in, const int* in_sizes, int n_in,
                              void* d_out, int out_size)
{
    const float* x   = (const float*)d_in[0];
    const int*   raw = (const int*)d_in[1];
    const float* Wq  = (const float*)d_in[2];
    const float* bq  = (const float*)d_in[3];
    const float* Wk  = (const float*)d_in[4];
    const float* bk  = (const float*)d_in[5];
    const float* Wv  = (const float*)d_in[6];
    const float* bv  = (const float*)d_in[7];
    float* out = (float*)d_out;

    decode_idx_kernel<<<1, 64>>>(raw);
    qkv_kernel<<<dim3(DD / 128, (BB * SS) / 128, 3), 256>>>(x, Wq, bq, Wk, bk, Wv, bv);
    scores_kernel<<<dim3(SS / 128, SS / 128, BB), 256>>>();
    softmax_kernel<<<dim3(SS / 8, PP, BB), 256>>>();
    av_kernel<<<dim3(DD / 128, SS / 128, BB * PP), 256>>>(out);
}

// round 5
// speedup vs baseline: 3.5321x; 1.1306x over previous
#include <cuda_runtime.h>
#include <math.h>
#include <stdint.h>

#define BB 2
#define SS 2048
#define DD 768
#define PP 16

// -------- scratch --------
__device__ float g_x[BB * SS * DD];          // tf32-truncated x
__device__ float g_w[3 * DD * DD];           // tf32-truncated Wq,Wk,Wv
__device__ float g_q[BB * SS * DD];
__device__ float g_k[BB * SS * DD];
__device__ float g_v[BB * SS * DD];
__device__ float g_sc[BB * SS * SS];
__device__ int   g_idx[BB * PP];

__global__ void decode_idx_kernel(const int* __restrict__ raw) {
    bool is64 = (raw[1] == 0);
    int t = threadIdx.x;
    if (t < BB * PP) g_idx[t] = is64 ? raw[2 * t] : raw[t];
}

// -------- tf32 helpers --------
__device__ __forceinline__ uint32_t f2tf(float f) {
    uint32_t u;
    asm("cvt.rna.tf32.f32 %0, %1;" : "=r"(u) : "f"(f));
    return u;
}

__device__ __forceinline__ void mma_tf32(float* c, const uint32_t* a, const uint32_t* b) {
    asm volatile(
        "mma.sync.aligned.m16n8k8.row.col.f32.tf32.tf32.f32 "
        "{%0,%1,%2,%3},{%4,%5,%6,%7},{%8,%9},{%0,%1,%2,%3};\n"
        : "+f"(c[0]), "+f"(c[1]), "+f"(c[2]), "+f"(c[3])
        : "r"(a[0]), "r"(a[1]), "r"(a[2]), "r"(a[3]), "r"(b[0]), "r"(b[1]));
}

// -------- cp.async helpers --------
__device__ __forceinline__ void cp16(uint32_t s, const void* g) {
    asm volatile("cp.async.cg.shared.global [%0], [%1], 16;\n" :: "r"(s), "l"(g));
}
__device__ __forceinline__ void cp16z(uint32_t s, const void* g, bool v) {
    int sz = v ? 16 : 0;
    asm volatile("cp.async.cg.shared.global [%0], [%1], 16, %2;\n" :: "r"(s), "l"(g), "r"(sz));
}
__device__ __forceinline__ void cp4z(uint32_t s, const void* g, bool v) {
    int sz = v ? 4 : 0;
    asm volatile("cp.async.ca.shared.global [%0], [%1], 4, %2;\n" :: "r"(s), "l"(g), "r"(sz));
}
#define CP_COMMIT asm volatile("cp.async.commit_group;\n")
#define CP_WAIT0  asm volatile("cp.async.wait_group 0;\n")

// -------- pre-truncate x and W to tf32 --------
__global__ __launch_bounds__(256) void trunc_kernel(
    const float* __restrict__ x,
    const float* __restrict__ Wq, const float* __restrict__ Wk, const float* __restrict__ Wv)
{
    const int NX = BB * SS * DD;   // 3,145,728
    const int NW = DD * DD;        //   589,824
    int stride = gridDim.x * blockDim.x;
    for (int i = blockIdx.x * blockDim.x + threadIdx.x; i < NX / 4; i += stride) {
        float4 v = *(const float4*)&x[i * 4];
        float4 o = {__uint_as_float(f2tf(v.x)), __uint_as_float(f2tf(v.y)),
                    __uint_as_float(f2tf(v.z)), __uint_as_float(f2tf(v.w))};
        *(float4*)&g_x[i * 4] = o;
    }
    for (int i = blockIdx.x * blockDim.x + threadIdx.x; i < NW / 4; i += stride) {
        float4 a = *(const float4*)&Wq[i * 4];
        float4 b = *(const float4*)&Wk[i * 4];
        float4 c = *(const float4*)&Wv[i * 4];
        float4 oa = {__uint_as_float(f2tf(a.x)), __uint_as_float(f2tf(a.y)),
                     __uint_as_float(f2tf(a.z)), __uint_as_float(f2tf(a.w))};
        float4 ob = {__uint_as_float(f2tf(b.x)), __uint_as_float(f2tf(b.y)),
                     __uint_as_float(f2tf(b.z)), __uint_as_float(f2tf(b.w))};
        float4 oc = {__uint_as_float(f2tf(c.x)), __uint_as_float(f2tf(c.y)),
                     __uint_as_float(f2tf(c.z)), __uint_as_float(f2tf(c.w))};
        *(float4*)&g_w[0 * NW + i * 4] = oa;
        *(float4*)&g_w[1 * NW + i * 4] = ob;
        *(float4*)&g_w[2 * NW + i * 4] = oc;
    }
}

// smem layout constants
#define A_STRIDE 36
#define B_STRIDE 132
#define A_BUFSZ (128 * A_STRIDE)     // floats, one stage
#define B_BUFSZ (32 * B_STRIDE)

extern __shared__ float dsm[];

// ============================================================
// Kernel 1: QKV.  C = Xt @ Wt + bias (inputs pre-truncated)
// 128x128 CTA tile, BK=32, cp.async double buffer.
// ============================================================
__global__ __launch_bounds__(256, 2) void qkv_kernel(
    const float* __restrict__ bq, const float* __restrict__ bk, const float* __restrict__ bv)
{
    const float* W = g_w + (size_t)blockIdx.z * DD * DD;
    const float* bias; float* out;
    if (blockIdx.z == 0)      { bias = bq; out = g_q; }
    else if (blockIdx.z == 1) { bias = bk; out = g_k; }
    else                      { bias = bv; out = g_v; }

    float* As = dsm;                       // [2][128][36]
    float* Bs = dsm + 2 * A_BUFSZ;         // [2][32][132]
    uint32_t As_u = (uint32_t)__cvta_generic_to_shared(As);
    uint32_t Bs_u = (uint32_t)__cvta_generic_to_shared(Bs);

    const int tid  = threadIdx.x;
    const int lane = tid & 31;
    const int warp = tid >> 5;
    const int wm = warp >> 2, wn = warp & 3;
    const int m0 = blockIdx.y * 128;
    const int n0 = blockIdx.x * 128;

    const int ar = tid >> 1, ac4 = tid & 1;        // A: 2 f4/row pairs? no: see loop
    float acc[4][4][4] = {};

    // stage issue: A tile 128x32 (1024 f4), B tile 32x128 (1024 f4)
    auto issue = [&](int kt, int buf) {
        int k0 = kt * 32;
        #pragma unroll
        for (int i = 0; i < 4; ++i) {
            int f4 = tid + i * 256;
            int r = f4 >> 3, c4 = f4 & 7;
            cp16(As_u + (buf * A_BUFSZ + r * A_STRIDE + c4 * 4) * 4,
                 &g_x[(size_t)(m0 + r) * DD + k0 + c4 * 4]);
        }
        #pragma unroll
        for (int i = 0; i < 4; ++i) {
            int f4 = tid + i * 256;
            int r = f4 >> 5, c4 = f4 & 31;
            cp16(Bs_u + (buf * B_BUFSZ + r * B_STRIDE + c4 * 4) * 4,
                 &W[(size_t)(k0 + r) * DD + n0 + c4 * 4]);
        }
    };

    const int KT = DD / 32;   // 24
    issue(0, 0); CP_COMMIT;

    for (int kt = 0; kt < KT; ++kt) {
        CP_WAIT0;
        __syncthreads();
        if (kt + 1 < KT) { issue(kt + 1, (kt + 1) & 1); CP_COMMIT; }
        const float* Ab = As + (kt & 1) * A_BUFSZ;
        const float* Bb = Bs + (kt & 1) * B_BUFSZ;
        #pragma unroll
        for (int ks = 0; ks < 32; ks += 8) {
            uint32_t a[4][4], b[4][2];
            #pragma unroll
            for (int mi = 0; mi < 4; ++mi) {
                int r = wm * 64 + mi * 16 + (lane >> 2);
                int c = ks + (lane & 3);
                a[mi][0] = __float_as_uint(Ab[r * A_STRIDE + c]);
                a[mi][1] = __float_as_uint(Ab[(r + 8) * A_STRIDE + c]);
                a[mi][2] = __float_as_uint(Ab[r * A_STRIDE + c + 4]);
                a[mi][3] = __float_as_uint(Ab[(r + 8) * A_STRIDE + c + 4]);
            }
            #pragma unroll
            for (int ni = 0; ni < 4; ++ni) {
                int c = wn * 32 + ni * 8 + (lane >> 2);
                int r = ks + (lane & 3);
                b[ni][0] = __float_as_uint(Bb[r * B_STRIDE + c]);
                b[ni][1] = __float_as_uint(Bb[(r + 4) * B_STRIDE + c]);
            }
            #pragma unroll
            for (int mi = 0; mi < 4; ++mi)
                #pragma unroll
                for (int ni = 0; ni < 4; ++ni)
                    mma_tf32(acc[mi][ni], a[mi], b[ni]);
        }
        __syncthreads();
    }

    #pragma unroll
    for (int mi = 0; mi < 4; ++mi) {
        #pragma unroll
        for (int ni = 0; ni < 4; ++ni) {
            int r = m0 + wm * 64 + mi * 16 + (lane >> 2);
            int c = n0 + wn * 32 + ni * 8 + (lane & 3) * 2;
            float b0 = bias[c], b1 = bias[c + 1];
            float2 o0 = {__uint_as_float(f2tf(acc[mi][ni][0] + b0)),
                         __uint_as_float(f2tf(acc[mi][ni][1] + b1))};
            float2 o1 = {__uint_as_float(f2tf(acc[mi][ni][2] + b0)),
                         __uint_as_float(f2tf(acc[mi][ni][3] + b1))};
            *(float2*)&out[(size_t)r * DD + c] = o0;
            *(float2*)&out[(size_t)(r + 8) * DD + c] = o1;
        }
    }
}

// ============================================================
// Kernel 2: scores = scale * Q @ K^T (Q,K already tf32-truncated)
// ============================================================
__global__ __launch_bounds__(256, 2) void scores_kernel()
{
    const int b = blockIdx.z;
    const float* Q = g_q + (size_t)b * SS * DD;
    const float* K = g_k + (size_t)b * SS * DD;
    float* Sc = g_sc + (size_t)b * SS * SS;

    float* Qs = dsm;                       // [2][128][36]
    float* Ks = dsm + 2 * A_BUFSZ;         // [2][128][36]
    uint32_t Qs_u = (uint32_t)__cvta_generic_to_shared(Qs);
    uint32_t Ks_u = (uint32_t)__cvta_generic_to_shared(Ks);

    const int tid  = threadIdx.x;
    const int lane = tid & 31;
    const int warp = tid >> 5;
    const int wm = warp >> 2, wn = warp & 3;
    const int m0 = blockIdx.y * 128;
    const int n0 = blockIdx.x * 128;

    float acc[4][4][4] = {};

    auto issue = [&](int kt, int buf) {
        int k0 = kt * 32;
        #pragma unroll
        for (int i = 0; i < 4; ++i) {
            int f4 = tid + i * 256;
            int r = f4 >> 3, c4 = f4 & 7;
            cp16(Qs_u + (buf * A_BUFSZ + r * A_STRIDE + c4 * 4) * 4,
                 &Q[(size_t)(m0 + r) * DD + k0 + c4 * 4]);
            cp16(Ks_u + (buf * A_BUFSZ + r * A_STRIDE + c4 * 4) * 4,
                 &K[(size_t)(n0 + r) * DD + k0 + c4 * 4]);
        }
    };

    const int KT = DD / 32;
    issue(0, 0); CP_COMMIT;

    for (int kt = 0; kt < KT; ++kt) {
        CP_WAIT0;
        __syncthreads();
        if (kt + 1 < KT) { issue(kt + 1, (kt + 1) & 1); CP_COMMIT; }
        const float* Qb = Qs + (kt & 1) * A_BUFSZ;
        const float* Kb = Ks + (kt & 1) * A_BUFSZ;
        #pragma unroll
        for (int ks = 0; ks < 32; ks += 8) {
            uint32_t a[4][4], bfr[4][2];
            #pragma unroll
            for (int mi = 0; mi < 4; ++mi) {
                int r = wm * 64 + mi * 16 + (lane >> 2);
                int c = ks + (lane & 3);
                a[mi][0] = __float_as_uint(Qb[r * A_STRIDE + c]);
                a[mi][1] = __float_as_uint(Qb[(r + 8) * A_STRIDE + c]);
                a[mi][2] = __float_as_uint(Qb[r * A_STRIDE + c + 4]);
                a[mi][3] = __float_as_uint(Qb[(r + 8) * A_STRIDE + c + 4]);
            }
            #pragma unroll
            for (int ni = 0; ni < 4; ++ni) {
                int n = wn * 32 + ni * 8 + (lane >> 2);
                int c = ks + (lane & 3);
                bfr[ni][0] = __float_as_uint(Kb[n * A_STRIDE + c]);
                bfr[ni][1] = __float_as_uint(Kb[n * A_STRIDE + c + 4]);
            }
            #pragma unroll
            for (int mi = 0; mi < 4; ++mi)
                #pragma unroll
                for (int ni = 0; ni < 4; ++ni)
                    mma_tf32(acc[mi][ni], a[mi], bfr[ni]);
        }
        __syncthreads();
    }

    const float scale = 0.03608439182435161f;
    #pragma unroll
    for (int mi = 0; mi < 4; ++mi) {
        #pragma unroll
        for (int ni = 0; ni < 4; ++ni) {
            int r = m0 + wm * 64 + mi * 16 + (lane >> 2);
            int c = n0 + wn * 32 + ni * 8 + (lane & 3) * 2;
            float2 o0 = {acc[mi][ni][0] * scale, acc[mi][ni][1] * scale};
            float2 o1 = {acc[mi][ni][2] * scale, acc[mi][ni][3] * scale};
            *(float2*)&Sc[(size_t)r * SS + c] = o0;
            *(float2*)&Sc[(size_t)(r + 8) * SS + c] = o1;
        }
    }
}

// ============================================================
// Kernel 3: segment softmax; writes tf32-truncated probabilities
// ============================================================
__global__ __launch_bounds__(256) void softmax_kernel()
{
    const int b = blockIdx.z;
    const int p = blockIdx.y;
    const int warp = threadIdx.x >> 5;
    const int lane = threadIdx.x & 31;
    const int q = blockIdx.x * 8 + warp;

    const int start = g_idx[b * PP + p];
    const int end   = (p == PP - 1) ? SS : g_idx[b * PP + p + 1];

    float* row = g_sc + ((size_t)b * SS + q) * SS;

    float m = -INFINITY;
    for (int j = start + lane; j < end; j += 32) m = fmaxf(m, row[j]);
    #pragma unroll
    for (int o = 16; o; o >>= 1) m = fmaxf(m, __shfl_xor_sync(0xFFFFFFFFu, m, o));

    float s = 0.f;
    for (int j = start + lane; j < end; j += 32) s += __expf(row[j] - m);
    #pragma unroll
    for (int o = 16; o; o >>= 1) s += __shfl_xor_sync(0xFFFFFFFFu, s, o);

    float inv = 1.f / s;
    for (int j = start + lane; j < end; j += 32)
        row[j] = __uint_as_float(f2tf(__expf(row[j] - m) * inv));
}

// ============================================================
// Kernel 4: out[bp] = P[:, start:end] @ V[start:end, :]
// ============================================================
__global__ __launch_bounds__(256, 2) void av_kernel(float* __restrict__ out)
{
    const int bp = blockIdx.z;
    const int b = bp / PP, p = bp % PP;
    const int start = g_idx[b * PP + p];
    const int end   = (p == PP - 1) ? SS : g_idx[b * PP + p + 1];
    const int L = end - start;

    const int m0 = blockIdx.y * 128;
    const int n0 = blockIdx.x * 128;
    const float* A = g_sc + (size_t)b * SS * SS;
    const float* V = g_v + (size_t)b * SS * DD;

    float* As = dsm;                       // [2][128][36]
    float* Bs = dsm + 2 * A_BUFSZ;         // [2][32][132]
    uint32_t As_u = (uint32_t)__cvta_generic_to_shared(As);
    uint32_t Bs_u = (uint32_t)__cvta_generic_to_shared(Bs);

    const int tid  = threadIdx.x;
    const int lane = tid & 31;
    const int warp = tid >> 5;
    const int wm = warp >> 2, wn = warp & 3;

    float acc[4][4][4] = {};

    auto issue = [&](int kt, int buf) {
        int k0 = kt * 32;
        // A tile: 128x32 scalar cp.async with zero fill (segment unaligned)
        #pragma unroll
        for (int i = 0; i < 16; ++i) {
            int sid = tid + i * 256;
            int m = sid >> 5, k = sid & 31;
            int j = start + k0 + k;
            cp4z(As_u + (buf * A_BUFSZ + m * A_STRIDE + k) * 4,
                 &A[(size_t)(m0 + m) * SS + j], j < end);
        }
        // V tile: 32x128 float4, row guarded
        #pragma unroll
        for (int i = 0; i < 4; ++i) {
            int f4 = tid + i * 256;
            int r = f4 >> 5, c4 = f4 & 31;
            int j = start + k0 + r;
            cp16z(Bs_u + (buf * B_BUFSZ + r * B_STRIDE + c4 * 4) * 4,
                  &V[(size_t)j * DD + n0 + c4 * 4], j < end);
        }
    };

    const int KT = (L + 31) / 32;
    issue(0, 0); CP_COMMIT;

    for (int kt = 0; kt < KT; ++kt) {
        CP_WAIT0;
        __syncthreads();
        if (kt + 1 < KT) { issue(kt + 1, (kt + 1) & 1); CP_COMMIT; }
        const float* Ab = As + (kt & 1) * A_BUFSZ;
        const float* Bb = Bs + (kt & 1) * B_BUFSZ;
        #pragma unroll
        for (int ks = 0; ks < 32; ks += 8) {
            uint32_t a[4][4], bfr[4][2];
            #pragma unroll
            for (int mi = 0; mi < 4; ++mi) {
                int r = wm * 64 + mi * 16 + (lane >> 2);
                int c = ks + (lane & 3);
                a[mi][0] = __float_as_uint(Ab[r * A_STRIDE + c]);
                a[mi][1] = __float_as_uint(Ab[(r + 8) * A_STRIDE + c]);
                a[mi][2] = __float_as_uint(Ab[r * A_STRIDE + c + 4]);
                a[mi][3] = __float_as_uint(Ab[(r + 8) * A_STRIDE + c + 4]);
            }
            #pragma unroll
            for (int ni = 0; ni < 4; ++ni) {
                int c = wn * 32 + ni * 8 + (lane >> 2);
                int r = ks + (lane & 3);
                bfr[ni][0] = __float_as_uint(Bb[r * B_STRIDE + c]);
                bfr[ni][1] = __float_as_uint(Bb[(r + 4) * B_STRIDE + c]);
            }
            #pragma unroll
            for (int mi = 0; mi < 4; ++mi)
                #pragma unroll
                for (int ni = 0; ni < 4; ++ni)
                    mma_tf32(acc[mi][ni], a[mi], bfr[ni]);
        }
        __syncthreads();
    }

    #pragma unroll
    for (int mi = 0; mi < 4; ++mi) {
        #pragma unroll
        for (int ni = 0; ni < 4; ++ni) {
            int r = m0 + wm * 64 + mi * 16 + (lane >> 2);
            int c = n0 + wn * 32 + ni * 8 + (lane & 3) * 2;
            float2 o0 = {acc[mi][ni][0], acc[mi][ni][1]};
            float2 o1 = {acc[mi][ni][2], acc[mi][ni][3]};
            *(float2*)&out[((size_t)bp * SS + r) * DD + c] = o0;
            *(float2*)&out[((size_t)bp * SS + r + 8) * DD + c] = o1;
        }
    }
}

// ============================================================
extern "C" void kernel_launch(void* const* d_in, const int* in_sizes, int n_in,
                              void* d_out, int out_size)
{
    const float* x   = (const float*)d_in[0];
    const int*   raw = (const int*)d_in[1];
    const float* Wq  = (const float*)d_in[2];
    const float* bq  = (const float*)d_in[3];
    const float* Wk  = (const float*)d_in[4];
    const float* bk  = (const float*)d_in[5];
    const float* Wv  = (const float*)d_in[6];
    const float* bv  = (const float*)d_in[7];
    float* out = (float*)d_out;

    const int qkv_smem = (2 * A_BUFSZ + 2 * B_BUFSZ) * 4;   // 70656 B
    const int sc_smem  = (4 * A_BUFSZ) * 4;                 // 73728 B
    const int av_smem  = (2 * A_BUFSZ + 2 * B_BUFSZ) * 4;   // 70656 B
    cudaFuncSetAttribute(qkv_kernel,    cudaFuncAttributeMaxDynamicSharedMemorySize, qkv_smem);
    cudaFuncSetAttribute(scores_kernel, cudaFuncAttributeMaxDynamicSharedMemorySize, sc_smem);
    cudaFuncSetAttribute(av_kernel,     cudaFuncAttributeMaxDynamicSharedMemorySize, av_smem);

    decode_idx_kernel<<<1, 64>>>(raw);
    trunc_kernel<<<512, 256>>>(x, Wq, Wk, Wv);
    qkv_kernel<<<dim3(DD / 128, (BB * SS) / 128, 3), 256, qkv_smem>>>(bq, bk, bv);
    scores_kernel<<<dim3(SS / 128, SS / 128, BB), 256, sc_smem>>>();
    softmax_kernel<<<dim3(SS / 8, PP, BB), 256>>>();
    av_kernel<<<dim3(DD / 128, SS / 128, BB * PP), 256, av_smem>>>(out);
}

// round 7
// speedup vs baseline: 5.2058x; 1.4739x over previous
#include <cuda_runtime.h>
#include <cuda_fp16.h>
#include <math.h>
#include <stdint.h>

#define BB 2
#define SS 2048
#define DD 768
#define PP 16

// -------- scratch --------
__device__ __half g_x[BB * SS * DD];         // fp16 x
__device__ __half g_wT[3 * DD * DD];         // fp16 transposed weights [z][n][k]
__device__ __half g_q[BB * SS * DD];         // fp16 q [b][s][d]
__device__ __half g_k[BB * SS * DD];         // fp16 k [b][s][d]
__device__ __half g_vT[BB * DD * SS];        // fp16 v transposed [b][d][s]
__device__ float  g_sc[BB * SS * SS];        // fp32 scores
__device__ __half g_p[BB * SS * SS];         // fp16 probabilities
__device__ int    g_idx[BB * PP];

__global__ void decode_idx_kernel(const int* __restrict__ raw) {
    bool is64 = (raw[1] == 0);
    int t = threadIdx.x;
    if (t < BB * PP) g_idx[t] = is64 ? raw[2 * t] : raw[t];
}

// -------- cp.async helpers --------
__device__ __forceinline__ void cp16(uint32_t s, const void* g) {
    asm volatile("cp.async.cg.shared.global [%0], [%1], 16;\n" :: "r"(s), "l"(g));
}
__device__ __forceinline__ void cp16z(uint32_t s, const void* g, bool v) {
    int sz = v ? 16 : 0;
    asm volatile("cp.async.cg.shared.global [%0], [%1], 16, %2;\n" :: "r"(s), "l"(g), "r"(sz));
}
#define CP_COMMIT asm volatile("cp.async.commit_group;\n")
#define CP_WAIT1  asm volatile("cp.async.wait_group 1;\n")

// -------- fp16 mma (m16n8k16, fp32 accum) --------
__device__ __forceinline__ void mma_fp16(float* c, const uint32_t* a, const uint32_t* b) {
    asm volatile(
        "mma.sync.aligned.m16n8k16.row.col.f32.f16.f16.f32 "
        "{%0,%1,%2,%3},{%4,%5,%6,%7},{%8,%9},{%0,%1,%2,%3};\n"
        : "+f"(c[0]), "+f"(c[1]), "+f"(c[2]), "+f"(c[3])
        : "r"(a[0]), "r"(a[1]), "r"(a[2]), "r"(a[3]), "r"(b[0]), "r"(b[1]));
}
__device__ __forceinline__ uint32_t lds2(const __half* p) { return *(const uint32_t*)p; }

// -------- prep: x -> fp16 --------
__global__ __launch_bounds__(256) void trunc_x_kernel(const float* __restrict__ x)
{
    const int NX = BB * SS * DD;
    int stride = gridDim.x * blockDim.x;
    for (int i = blockIdx.x * blockDim.x + threadIdx.x; i < NX / 4; i += stride) {
        float4 v = *(const float4*)&x[i * 4];
        __half2 h0 = __floats2half2_rn(v.x, v.y);
        __half2 h1 = __floats2half2_rn(v.z, v.w);
        *(uint2*)&g_x[i * 4] = make_uint2(*(uint32_t*)&h0, *(uint32_t*)&h1);
    }
}

// -------- prep: W[k][n] -> g_wT[z][n][k] fp16 --------
__global__ __launch_bounds__(256) void transw_kernel(
    const float* __restrict__ Wq, const float* __restrict__ Wk, const float* __restrict__ Wv)
{
    __shared__ float t[32][33];
    const int z = blockIdx.z;
    const float* W = (z == 0) ? Wq : (z == 1) ? Wk : Wv;
    const int n0 = blockIdx.x * 32, k0 = blockIdx.y * 32;
    for (int i = threadIdx.y; i < 32; i += 8)
        t[i][threadIdx.x] = W[(size_t)(k0 + i) * DD + n0 + threadIdx.x];
    __syncthreads();
    for (int i = threadIdx.y; i < 32; i += 8)
        g_wT[(size_t)z * DD * DD + (size_t)(n0 + i) * DD + k0 + threadIdx.x] =
            __float2half(t[threadIdx.x][i]);
}

// ============================================================
// Unified fp16 GEMM: D[128,128] = A[128,K] @ B[128,K]^T
// MODE 0: QKV  (A=g_x, B=g_wT[z]; +bias; z=2 writes vT)
// MODE 1: scores (A=g_q[b], B=g_k[b]; *scale -> fp32 g_sc)
// MODE 2: AV   (A=g_p[b], B=g_vT[b]; segment [start,end))
// 256 thr, 8 warps (2x4), warp tile 64x32, BK=32, 3-stage cp.async.
// ============================================================
#define A_ST 40                      // fp16 elems per smem row (80B, conflict-free)
#define TILE_BYTES (128 * A_ST * 2)  // 10240
#define STG_BYTES  (2 * TILE_BYTES)  // A + B per stage
#define SMEM_TOTAL (3 * STG_BYTES)   // 61440

extern __shared__ char dsm[];

template<int MODE>
__global__ __launch_bounds__(256, 2) void hgemm_kernel(
    const float* __restrict__ bq, const float* __restrict__ bk,
    const float* __restrict__ bv, float* __restrict__ out_av)
{
    const int tid  = threadIdx.x;
    const int lane = tid & 31;
    const int warp = tid >> 5;
    const int wm = warp >> 2, wn = warp & 3;
    const int m0 = blockIdx.y * 128;
    const int n0 = blockIdx.x * 128;
    const int c2 = (lane & 3) * 2;
    const int qr = lane >> 2;

    const __half* Ab; const __half* Bb;
    int lda, ldb, base = 0, start = 0, end = 1 << 30, KT;
    if (MODE == 0) {
        Ab = g_x; lda = DD;
        Bb = g_wT + (size_t)blockIdx.z * DD * DD; ldb = DD;
        KT = DD / 32;
    } else if (MODE == 1) {
        Ab = g_q + (size_t)blockIdx.z * SS * DD; lda = DD;
        Bb = g_k + (size_t)blockIdx.z * SS * DD; ldb = DD;
        KT = DD / 32;
    } else {
        int bp = blockIdx.z, b = bp / PP, p = bp % PP;
        start = g_idx[b * PP + p];
        end   = (p == PP - 1) ? SS : g_idx[b * PP + p + 1];
        base  = start & ~31;
        Ab = g_p + (size_t)b * SS * SS; lda = SS;
        Bb = g_vT + (size_t)b * DD * SS; ldb = SS;
        KT = (end - base + 31) / 32;
    }

    const uint32_t smb = (uint32_t)__cvta_generic_to_shared(dsm);
    float acc[4][4][4] = {};

    auto issue = [&](int kt) {
        if (kt < KT) {
            int st = kt % 3;
            uint32_t sa = smb + st * STG_BYTES;
            uint32_t sb = sa + TILE_BYTES;
            int k0 = base + kt * 32;
            #pragma unroll
            for (int i = 0; i < 2; ++i) {
                int id = tid + i * 256;             // 0..511
                int r = id >> 2, c = id & 3;
                int j = k0 + c * 8;
                if (MODE == 2) {
                    cp16z(sa + r * (A_ST * 2) + c * 16, Ab + (size_t)(m0 + r) * lda + j, j < SS);
                    cp16z(sb + r * (A_ST * 2) + c * 16, Bb + (size_t)(n0 + r) * ldb + j, j < SS);
                } else {
                    cp16(sa + r * (A_ST * 2) + c * 16, Ab + (size_t)(m0 + r) * lda + j);
                    cp16(sb + r * (A_ST * 2) + c * 16, Bb + (size_t)(n0 + r) * ldb + j);
                }
            }
        }
        CP_COMMIT;
    };

    issue(0); issue(1);

    for (int kt = 0; kt < KT; ++kt) {
        CP_WAIT1;
        __syncthreads();

        __half* sA = (__half*)(dsm + (kt % 3) * STG_BYTES);
        __half* sB = sA + 128 * A_ST;

        if (MODE == 2) {
            int rel = base + kt * 32;
            int lo = start - rel;           // >0 only on first stage
            int hi = end - rel;             // <32 only on last stage
            if (lo > 0 || hi < 32) {
                int lo_c = lo > 0 ? lo : 0;
                int hi_c = hi < 32 ? hi : 32;
                for (int idx = tid; idx < 128 * 32; idx += 256) {
                    int r = idx >> 5, c = idx & 31;
                    if (c < lo_c || c >= hi_c) sA[r * A_ST + c] = __ushort_as_half(0);
                }
                __syncthreads();
            }
        }

        issue(kt + 2);

        #pragma unroll
        for (int ks = 0; ks < 32; ks += 16) {
            uint32_t a[4][4], b[4][2];
            #pragma unroll
            for (int mi = 0; mi < 4; ++mi) {
                int r = wm * 64 + mi * 16 + qr;
                a[mi][0] = lds2(sA + r * A_ST + ks + c2);
                a[mi][1] = lds2(sA + (r + 8) * A_ST + ks + c2);
                a[mi][2] = lds2(sA + r * A_ST + ks + c2 + 8);
                a[mi][3] = lds2(sA + (r + 8) * A_ST + ks + c2 + 8);
            }
            #pragma unroll
            for (int ni = 0; ni < 4; ++ni) {
                int n = wn * 32 + ni * 8 + qr;
                b[ni][0] = lds2(sB + n * A_ST + ks + c2);
                b[ni][1] = lds2(sB + n * A_ST + ks + c2 + 8);
            }
            #pragma unroll
            for (int mi = 0; mi < 4; ++mi)
                #pragma unroll
                for (int ni = 0; ni < 4; ++ni)
                    mma_fp16(acc[mi][ni], a[mi], b[ni]);
        }
    }

    // ---- epilogue ----
    #pragma unroll
    for (int mi = 0; mi < 4; ++mi) {
        #pragma unroll
        for (int ni = 0; ni < 4; ++ni) {
            int r = m0 + wm * 64 + mi * 16 + qr;
            int c = n0 + wn * 32 + ni * 8 + c2;
            float v00 = acc[mi][ni][0], v01 = acc[mi][ni][1];
            float v10 = acc[mi][ni][2], v11 = acc[mi][ni][3];
            if (MODE == 0) {
                const int z = blockIdx.z;
                const float* bias = (z == 0) ? bq : (z == 1) ? bk : bv;
                float b0 = bias[c], b1 = bias[c + 1];
                if (z < 2) {
                    __half* outp = (z == 0) ? g_q : g_k;
                    __half2 h0 = __floats2half2_rn(v00 + b0, v01 + b1);
                    __half2 h1 = __floats2half2_rn(v10 + b0, v11 + b1);
                    *(uint32_t*)&outp[(size_t)r * DD + c] = *(uint32_t*)&h0;
                    *(uint32_t*)&outp[(size_t)(r + 8) * DD + c] = *(uint32_t*)&h1;
                } else {
                    // V transposed: g_vT[b][d][s]
                    int b_i = r >> 11, s = r & (SS - 1);
                    int b_j = (r + 8) >> 11, s2 = (r + 8) & (SS - 1);
                    g_vT[((size_t)b_i * DD + c) * SS + s]      = __float2half(v00 + b0);
                    g_vT[((size_t)b_i * DD + c + 1) * SS + s]  = __float2half(v01 + b1);
                    g_vT[((size_t)b_j * DD + c) * SS + s2]     = __float2half(v10 + b0);
                    g_vT[((size_t)b_j * DD + c + 1) * SS + s2] = __float2half(v11 + b1);
                }
            } else if (MODE == 1) {
                const float scale = 0.03608439182435161f;
                float* Sc = g_sc + (size_t)blockIdx.z * SS * SS;
                float2 o0 = {v00 * scale, v01 * scale};
                float2 o1 = {v10 * scale, v11 * scale};
                *(float2*)&Sc[(size_t)r * SS + c] = o0;
                *(float2*)&Sc[(size_t)(r + 8) * SS + c] = o1;
            } else {
                const int bp = blockIdx.z;
                float2 o0 = {v00, v01};
                float2 o1 = {v10, v11};
                *(float2*)&out_av[((size_t)bp * SS + r) * DD + c] = o0;
                *(float2*)&out_av[((size_t)bp * SS + r + 8) * DD + c] = o1;
            }
        }
    }
}

// ============================================================
// segment softmax: fp32 scores in, fp16 probabilities out
// ============================================================
__global__ __launch_bounds__(256) void softmax_kernel()
{
    const int b = blockIdx.z;
    const int p = blockIdx.y;
    const int warp = threadIdx.x >> 5;
    const int lane = threadIdx.x & 31;
    const int q = blockIdx.x * 8 + warp;

    const int start = g_idx[b * PP + p];
    const int end   = (p == PP - 1) ? SS : g_idx[b * PP + p + 1];

    const float* row = g_sc + ((size_t)b * SS + q) * SS;
    __half* prow = g_p + ((size_t)b * SS + q) * SS;

    float m = -INFINITY;
    for (int j = start + lane; j < end; j += 32) m = fmaxf(m, row[j]);
    #pragma unroll
    for (int o = 16; o; o >>= 1) m = fmaxf(m, __shfl_xor_sync(0xFFFFFFFFu, m, o));

    float s = 0.f;
    for (int j = start + lane; j < end; j += 32) s += __expf(row[j] - m);
    #pragma unroll
    for (int o = 16; o; o >>= 1) s += __shfl_xor_sync(0xFFFFFFFFu, s, o);

    float inv = 1.f / s;
    for (int j = start + lane; j < end; j += 32)
        prow[j] = __float2half(__expf(row[j] - m) * inv);
}

// ============================================================
extern "C" void kernel_launch(void* const* d_in, const int* in_sizes, int n_in,
                              void* d_out, int out_size)
{
    const float* x   = (const float*)d_in[0];
    const int*   raw = (const int*)d_in[1];
    const float* Wq  = (const float*)d_in[2];
    const float* bq  = (const float*)d_in[3];
    const float* Wk  = (const float*)d_in[4];
    const float* bk  = (const float*)d_in[5];
    const float* Wv  = (const float*)d_in[6];
    const float* bv  = (const float*)d_in[7];
    float* out = (float*)d_out;

    cudaFuncSetAttribute(hgemm_kernel<0>, cudaFuncAttributeMaxDynamicSharedMemorySize, SMEM_TOTAL);
    cudaFuncSetAttribute(hgemm_kernel<1>, cudaFuncAttributeMaxDynamicSharedMemorySize, SMEM_TOTAL);
    cudaFuncSetAttribute(hgemm_kernel<2>, cudaFuncAttributeMaxDynamicSharedMemorySize, SMEM_TOTAL);

    decode_idx_kernel<<<1, 64>>>(raw);
    trunc_x_kernel<<<512, 256>>>(x);
    transw_kernel<<<dim3(DD / 32, DD / 32, 3), dim3(32, 8)>>>(Wq, Wk, Wv);
    hgemm_kernel<0><<<dim3(DD / 128, (BB * SS) / 128, 3), 256, SMEM_TOTAL>>>(bq, bk, bv, out);
    hgemm_kernel<1><<<dim3(SS / 128, SS / 128, BB), 256, SMEM_TOTAL>>>(bq, bk, bv, out);
    softmax_kernel<<<dim3(SS / 8, PP, BB), 256>>>();
    hgemm_kernel<2><<<dim3(DD / 128, SS / 128, BB * PP), 256, SMEM_TOTAL>>>(bq, bk, bv, out);
}

// round 8
// speedup vs baseline: 5.6377x; 1.0830x over previous
#include <cuda_runtime.h>
#include <cuda_fp16.h>
#include <math.h>
#include <stdint.h>

#define BB 2
#define SS 2048
#define DD 768
#define PP 16

// -------- scratch --------
__device__ __half g_x[BB * SS * DD];
__device__ __half g_wT[3 * DD * DD];         // [z][n][k]
__device__ __half g_q[BB * SS * DD];
__device__ __half g_k[BB * SS * DD];
__device__ __half g_vT[BB * DD * SS];        // [b][d][s]
__device__ float  g_sc[BB * SS * SS];
__device__ __half g_p[BB * SS * SS];
__device__ int    g_idx[BB * PP];

__global__ void decode_idx_kernel(const int* __restrict__ raw) {
    bool is64 = (raw[1] == 0);
    int t = threadIdx.x;
    if (t < BB * PP) g_idx[t] = is64 ? raw[2 * t] : raw[t];
}

// -------- cp.async --------
__device__ __forceinline__ void cp16(uint32_t s, const void* g) {
    asm volatile("cp.async.cg.shared.global [%0], [%1], 16;\n" :: "r"(s), "l"(g));
}
#define CP_COMMIT asm volatile("cp.async.commit_group;\n")
#define CP_WAIT1  asm volatile("cp.async.wait_group 1;\n")

// -------- mma / ldmatrix --------
__device__ __forceinline__ void mma_fp16(float* c, const uint32_t* a, const uint32_t* b) {
    asm volatile(
        "mma.sync.aligned.m16n8k16.row.col.f32.f16.f16.f32 "
        "{%0,%1,%2,%3},{%4,%5,%6,%7},{%8,%9},{%0,%1,%2,%3};\n"
        : "+f"(c[0]), "+f"(c[1]), "+f"(c[2]), "+f"(c[3])
        : "r"(a[0]), "r"(a[1]), "r"(a[2]), "r"(a[3]), "r"(b[0]), "r"(b[1]));
}
__device__ __forceinline__ void ldsm4(uint32_t& r0, uint32_t& r1, uint32_t& r2,
                                      uint32_t& r3, uint32_t addr) {
    asm volatile("ldmatrix.sync.aligned.m8n8.x4.shared.b16 {%0,%1,%2,%3}, [%4];"
                 : "=r"(r0), "=r"(r1), "=r"(r2), "=r"(r3) : "r"(addr));
}

// -------- prep --------
__global__ __launch_bounds__(256) void trunc_x_kernel(const float* __restrict__ x)
{
    const int NX = BB * SS * DD;
    int stride = gridDim.x * blockDim.x;
    for (int i = blockIdx.x * blockDim.x + threadIdx.x; i < NX / 4; i += stride) {
        float4 v = *(const float4*)&x[i * 4];
        __half2 h0 = __floats2half2_rn(v.x, v.y);
        __half2 h1 = __floats2half2_rn(v.z, v.w);
        *(uint2*)&g_x[i * 4] = make_uint2(*(uint32_t*)&h0, *(uint32_t*)&h1);
    }
}

__global__ __launch_bounds__(256) void transw_kernel(
    const float* __restrict__ Wq, const float* __restrict__ Wk, const float* __restrict__ Wv)
{
    __shared__ float t[32][33];
    const int z = blockIdx.z;
    const float* W = (z == 0) ? Wq : (z == 1) ? Wk : Wv;
    const int n0 = blockIdx.x * 32, k0 = blockIdx.y * 32;
    for (int i = threadIdx.y; i < 32; i += 8)
        t[i][threadIdx.x] = W[(size_t)(k0 + i) * DD + n0 + threadIdx.x];
    __syncthreads();
    for (int i = threadIdx.y; i < 32; i += 8)
        g_wT[(size_t)z * DD * DD + (size_t)(n0 + i) * DD + k0 + threadIdx.x] =
            __float2half(t[threadIdx.x][i]);
}

// ============================================================
// fp16 GEMM: D[128,128] = A[128,K] @ B[128,K]^T
// BK=64 halfs (128B rows, SW128 swizzle), 3-stage cp.async,
// ldmatrix fragment loads. 8 warps (2x4), warp tile 64x32.
// ============================================================
#define TILE_B (128 * 128)           // bytes per tile (128 rows x 128B)
#define STG_B  (2 * TILE_B)          // A + B
#define SMEM_TOTAL (3 * STG_B)       // 98304

extern __shared__ char dsm[];

template<int MODE>
__global__ __launch_bounds__(256, 2) void hgemm_kernel(
    const float* __restrict__ bq, const float* __restrict__ bk,
    const float* __restrict__ bv, float* __restrict__ out_av)
{
    const int tid  = threadIdx.x;
    const int lane = tid & 31;
    const int warp = tid >> 5;
    const int wm = warp >> 2, wn = warp & 3;
    const int m0 = blockIdx.y * 128;
    const int n0 = blockIdx.x * 128;
    const int c2 = (lane & 3) * 2;
    const int qr = lane >> 2;

    const __half* Ab; const __half* Bb;
    int lda, ldb, base = 0, start = 0, end = 1 << 30, KT;
    if (MODE == 0) {
        Ab = g_x; lda = DD;
        Bb = g_wT + (size_t)blockIdx.z * DD * DD; ldb = DD;
        KT = DD / 64;
    } else if (MODE == 1) {
        Ab = g_q + (size_t)blockIdx.z * SS * DD; lda = DD;
        Bb = g_k + (size_t)blockIdx.z * SS * DD; ldb = DD;
        KT = DD / 64;
    } else {
        int bp = blockIdx.z, b = bp / PP, p = bp % PP;
        start = g_idx[b * PP + p];
        end   = (p == PP - 1) ? SS : g_idx[b * PP + p + 1];
        base  = start & ~63;
        Ab = g_p + (size_t)b * SS * SS; lda = SS;
        Bb = g_vT + (size_t)b * DD * SS; ldb = SS;
        KT = (end - base + 63) / 64;
    }

    const uint32_t smb = (uint32_t)__cvta_generic_to_shared(dsm);
    float acc[4][4][4] = {};

    // ldmatrix per-lane invariants
    const int lrow = ((lane >> 3) & 1) * 8 + (lane & 7);   // row within 16-row tile
    const int lcadd = lane >> 4;                           // chunk add (0/1)

    auto issue = [&](int kt) {
        if (kt < KT) {
            uint32_t sa = smb + (kt % 3) * STG_B;
            uint32_t sb = sa + TILE_B;
            int k0 = base + kt * 64;
            #pragma unroll
            for (int i = 0; i < 4; ++i) {
                int id = tid + i * 256;              // 0..1023
                int r = id >> 3, c = id & 7;
                uint32_t sw = (uint32_t)(r * 128 + ((c ^ (r & 7)) * 16));
                cp16(sa + sw, Ab + (size_t)(m0 + r) * lda + k0 + c * 8);
                cp16(sb + sw, Bb + (size_t)(n0 + r) * ldb + k0 + c * 8);
            }
        }
        CP_COMMIT;
    };

    issue(0); issue(1);

    for (int kt = 0; kt < KT; ++kt) {
        CP_WAIT1;
        __syncthreads();

        uint32_t sa = smb + (kt % 3) * STG_B;
        uint32_t sb = sa + TILE_B;

        if (MODE == 2) {
            int rel = base + kt * 64;
            int lo = start - rel;
            int hi = end - rel;
            if (lo > 0 || hi < 64) {
                int lo_c = lo > 0 ? lo : 0;
                int hi_c = hi < 64 ? hi : 64;
                __half* sAh = (__half*)(dsm + (kt % 3) * STG_B);
                for (int idx = tid; idx < 128 * 64; idx += 256) {
                    int r = idx >> 6, c = idx & 63;
                    if (c < lo_c || c >= hi_c) {
                        uint32_t off = (uint32_t)(r * 128 + c * 2);
                        uint32_t sw = off ^ ((off >> 3) & 0x70);
                        *(__half*)((char*)sAh + sw) = __ushort_as_half(0);
                    }
                }
                __syncthreads();
            }
        }

        issue(kt + 2);

        #pragma unroll
        for (int ks = 0; ks < 64; ks += 16) {
            const int kc = ks >> 3;                 // 0,2,4,6
            uint32_t a[4][4], b[4][2];
            #pragma unroll
            for (int mi = 0; mi < 4; ++mi) {
                int row = wm * 64 + mi * 16 + lrow;
                uint32_t addr = sa + row * 128 + (((kc + lcadd) ^ (row & 7)) * 16);
                ldsm4(a[mi][0], a[mi][1], a[mi][2], a[mi][3], addr);
            }
            #pragma unroll
            for (int pr = 0; pr < 2; ++pr) {
                int nrow = wn * 32 + pr * 16 + lrow;
                uint32_t addr = sb + nrow * 128 + (((kc + lcadd) ^ (nrow & 7)) * 16);
                uint32_t r0, r1, r2, r3;
                ldsm4(r0, r1, r2, r3, addr);
                b[pr * 2][0] = r0;     b[pr * 2][1] = r2;
                b[pr * 2 + 1][0] = r1; b[pr * 2 + 1][1] = r3;
            }
            #pragma unroll
            for (int mi = 0; mi < 4; ++mi)
                #pragma unroll
                for (int ni = 0; ni < 4; ++ni)
                    mma_fp16(acc[mi][ni], a[mi], b[ni]);
        }
    }

    // ---- epilogue ----
    #pragma unroll
    for (int mi = 0; mi < 4; ++mi) {
        #pragma unroll
        for (int ni = 0; ni < 4; ++ni) {
            int r = m0 + wm * 64 + mi * 16 + qr;
            int c = n0 + wn * 32 + ni * 8 + c2;
            float v00 = acc[mi][ni][0], v01 = acc[mi][ni][1];
            float v10 = acc[mi][ni][2], v11 = acc[mi][ni][3];
            if (MODE == 0) {
                const int z = blockIdx.z;
                const float* bias = (z == 0) ? bq : (z == 1) ? bk : bv;
                float b0 = bias[c], b1 = bias[c + 1];
                if (z < 2) {
                    __half* outp = (z == 0) ? g_q : g_k;
                    __half2 h0 = __floats2half2_rn(v00 + b0, v01 + b1);
                    __half2 h1 = __floats2half2_rn(v10 + b0, v11 + b1);
                    *(uint32_t*)&outp[(size_t)r * DD + c] = *(uint32_t*)&h0;
                    *(uint32_t*)&outp[(size_t)(r + 8) * DD + c] = *(uint32_t*)&h1;
                } else {
                    int b_i = r >> 11, s = r & (SS - 1);
                    int b_j = (r + 8) >> 11, s2 = (r + 8) & (SS - 1);
                    g_vT[((size_t)b_i * DD + c) * SS + s]      = __float2half(v00 + b0);
                    g_vT[((size_t)b_i * DD + c + 1) * SS + s]  = __float2half(v01 + b1);
                    g_vT[((size_t)b_j * DD + c) * SS + s2]     = __float2half(v10 + b0);
                    g_vT[((size_t)b_j * DD + c + 1) * SS + s2] = __float2half(v11 + b1);
                }
            } else if (MODE == 1) {
                const float scale = 0.03608439182435161f;
                float* Sc = g_sc + (size_t)blockIdx.z * SS * SS;
                float2 o0 = {v00 * scale, v01 * scale};
                float2 o1 = {v10 * scale, v11 * scale};
                *(float2*)&Sc[(size_t)r * SS + c] = o0;
                *(float2*)&Sc[(size_t)(r + 8) * SS + c] = o1;
            } else {
                const int bp = blockIdx.z;
                float2 o0 = {v00, v01};
                float2 o1 = {v10, v11};
                *(float2*)&out_av[((size_t)bp * SS + r) * DD + c] = o0;
                *(float2*)&out_av[((size_t)bp * SS + r + 8) * DD + c] = o1;
            }
        }
    }
}

// ============================================================
// segment softmax: fp32 scores in, fp16 probs out
// ============================================================
__global__ __launch_bounds__(256) void softmax_kernel()
{
    const int b = blockIdx.z;
    const int p = blockIdx.y;
    const int warp = threadIdx.x >> 5;
    const int lane = threadIdx.x & 31;
    const int q = blockIdx.x * 8 + warp;

    const int start = g_idx[b * PP + p];
    const int end   = (p == PP - 1) ? SS : g_idx[b * PP + p + 1];

    const float* row = g_sc + ((size_t)b * SS + q) * SS;
    __half* prow = g_p + ((size_t)b * SS + q) * SS;

    float m = -INFINITY;
    for (int j = start + lane; j < end; j += 32) m = fmaxf(m, row[j]);
    #pragma unroll
    for (int o = 16; o; o >>= 1) m = fmaxf(m, __shfl_xor_sync(0xFFFFFFFFu, m, o));

    float s = 0.f;
    for (int j = start + lane; j < end; j += 32) s += __expf(row[j] - m);
    #pragma unroll
    for (int o = 16; o; o >>= 1) s += __shfl_xor_sync(0xFFFFFFFFu, s, o);

    float inv = 1.f / s;
    for (int j = start + lane; j < end; j += 32)
        prow[j] = __float2half(__expf(row[j] - m) * inv);
}

// ============================================================
extern "C" void kernel_launch(void* const* d_in, const int* in_sizes, int n_in,
                              void* d_out, int out_size)
{
    const float* x   = (const float*)d_in[0];
    const int*   raw = (const int*)d_in[1];
    const float* Wq  = (const float*)d_in[2];
    const float* bq  = (const float*)d_in[3];
    const float* Wk  = (const float*)d_in[4];
    const float* bk  = (const float*)d_in[5];
    const float* Wv  = (const float*)d_in[6];
    const float* bv  = (const float*)d_in[7];
    float* out = (float*)d_out;

    cudaFuncSetAttribute(hgemm_kernel<0>, cudaFuncAttributeMaxDynamicSharedMemorySize, SMEM_TOTAL);
    cudaFuncSetAttribute(hgemm_kernel<1>, cudaFuncAttributeMaxDynamicSharedMemorySize, SMEM_TOTAL);
    cudaFuncSetAttribute(hgemm_kernel<2>, cudaFuncAttributeMaxDynamicSharedMemorySize, SMEM_TOTAL);

    decode_idx_kernel<<<1, 64>>>(raw);
    trunc_x_kernel<<<512, 256>>>(x);
    transw_kernel<<<dim3(DD / 32, DD / 32, 3), dim3(32, 8)>>>(Wq, Wk, Wv);
    hgemm_kernel<0><<<dim3(DD / 128, (BB * SS) / 128, 3), 256, SMEM_TOTAL>>>(bq, bk, bv, out);
    hgemm_kernel<1><<<dim3(SS / 128, SS / 128, BB), 256, SMEM_TOTAL>>>(bq, bk, bv, out);
    softmax_kernel<<<dim3(SS / 8, PP, BB), 256>>>();
    hgemm_kernel<2><<<dim3(DD / 128, SS / 128, BB * PP), 256, SMEM_TOTAL>>>(bq, bk, bv, out);
}